// round 1
// baseline (speedup 1.0000x reference)
#include <cuda_runtime.h>
#include <math.h>

#define BB 2
#define TT 2048
#define EE 512
#define NHH 8
#define HDD 64
#define BHH (BB*NHH)
#define E3 (3*EE)

static __device__ __constant__ const float SCALE = 0.125f; // 64^-0.5

// Scratch (no allocations allowed)
__device__ float g_qkv[(size_t)BB * TT * E3];    // 25 MB
__device__ float g_params[(size_t)BHH * TT * 6]; // per (bh,t): bl, br, wbl, wbr, al, frac
__device__ float g_attn[(size_t)BB * TT * EE];   // 8 MB

// ---------------------------------------------------------------------------
// Generic tiled fp32 GEMM: C[M,N] = A[M,K] @ W[K,N] + bias[N]
// BM=BN=64, BK=16, 256 threads, 4x4 register tile per thread.
// ---------------------------------------------------------------------------
__global__ __launch_bounds__(256) void gemm_bias_kernel(
    const float* __restrict__ A, const float* __restrict__ W,
    const float* __restrict__ bias, float* __restrict__ C,
    int M, int N, int K)
{
    __shared__ float As[64][17];
    __shared__ float Bs[16][64];

    int bm = blockIdx.y * 64;
    int bn = blockIdx.x * 64;
    int tid = threadIdx.x;
    int tx = tid & 15, ty = tid >> 4;

    float acc[4][4];
#pragma unroll
    for (int i = 0; i < 4; i++)
#pragma unroll
        for (int j = 0; j < 4; j++) acc[i][j] = 0.f;

    for (int k0 = 0; k0 < K; k0 += 16) {
#pragma unroll
        for (int idx = tid; idx < 64 * 16; idx += 256) {
            int r = idx >> 4, c = idx & 15;
            As[r][c] = A[(size_t)(bm + r) * K + (k0 + c)];
        }
#pragma unroll
        for (int idx = tid; idx < 16 * 64; idx += 256) {
            int r = idx >> 6, c = idx & 63;
            Bs[r][c] = W[(size_t)(k0 + r) * N + (bn + c)];
        }
        __syncthreads();
#pragma unroll
        for (int k = 0; k < 16; k++) {
            float a[4], b[4];
#pragma unroll
            for (int i = 0; i < 4; i++) a[i] = As[ty * 4 + i][k];
#pragma unroll
            for (int j = 0; j < 4; j++) b[j] = Bs[k][tx * 4 + j];
#pragma unroll
            for (int i = 0; i < 4; i++)
#pragma unroll
                for (int j = 0; j < 4; j++)
                    acc[i][j] = fmaf(a[i], b[j], acc[i][j]);
        }
        __syncthreads();
    }

#pragma unroll
    for (int i = 0; i < 4; i++) {
        int row = bm + ty * 4 + i;
#pragma unroll
        for (int j = 0; j < 4; j++) {
            int col = bn + tx * 4 + j;
            C[(size_t)row * N + col] = acc[i][j] + bias[col];
        }
    }
}

// ---------------------------------------------------------------------------
// od kernel: for each (b,t) compute od[16] = Q_row @ w_od + b_od, then derive
// the 6 per-(head,query) deformable-window scalars.
// ---------------------------------------------------------------------------
__global__ __launch_bounds__(128) void od_kernel(
    const float* __restrict__ w_od, const float* __restrict__ b_od)
{
    int bt = blockIdx.x;            // b*T + t
    int b = bt / TT, t = bt % TT;
    const float* qrow = g_qkv + (size_t)bt * E3;  // Q slice is first E floats

    int tid = threadIdx.x;          // 128 threads
    int c = tid & 15, r = tid >> 4; // 16 outputs x 8 partial lanes

    float partial = 0.f;
    for (int k = r; k < EE; k += 8)
        partial = fmaf(qrow[k], w_od[k * 16 + c], partial);

    __shared__ float red[128];
    __shared__ float odv[16];
    red[tid] = partial;
    __syncthreads();
    if (tid < 16) {
        float s = 0.f;
#pragma unroll
        for (int rr = 0; rr < 8; rr++) s += red[tid + 16 * rr];
        odv[tid] = s + b_od[tid];
    }
    __syncthreads();
    if (tid < NHH) {
        int h = tid;
        float off = tanhf(odv[h]) * (float)TT;
        float dur = (float)TT / (1.f + expf(-odv[h + NHH]));
        float anchor = (float)t + off;
        float start = anchor - dur;
        float end   = anchor + dur;
        float bl = floorf(start);
        float br = ceilf(end);
        float al = floorf(anchor);
        float fr = anchor - al;
        float* p = g_params + ((size_t)(b * NHH + h) * TT + t) * 6;
        p[0] = bl;
        p[1] = br;
        p[2] = bl - start;   // <= 0
        p[3] = end - br;     // <= 0
        p[4] = al;
        p[5] = fr;
    }
}

// ---------------------------------------------------------------------------
// Flash-style deformable attention.
// Grid: (T/32, B*NH). 256 threads. Each thread: query q = tid/8, group g = tid%8.
// Per j-tile of 32: thread computes 4 scores (j = g*4..g*4+3) and owns 8 output
// dims (c = cc*8 + g).
// ---------------------------------------------------------------------------
__global__ __launch_bounds__(256) void attn_kernel()
{
    __shared__ float Qs[32][65];
    __shared__ float Ks[32][65];
    __shared__ float Vs[32][65];
    __shared__ float Ps[32][33];

    int qt = blockIdx.x;
    int bh = blockIdx.y;
    int b = bh / NHH, h = bh % NHH;
    int tid = threadIdx.x;
    int q = tid >> 3;   // 0..31
    int g = tid & 7;    // 0..7
    int i = qt * 32 + q;

    // Load Q tile (Q section starts at offset 0 within the 3E row)
    const float* qbase = g_qkv + ((size_t)(b * TT) + qt * 32) * E3 + h * HDD;
#pragma unroll
    for (int idx = tid; idx < 32 * 64; idx += 256) {
        int r = idx >> 6, c = idx & 63;
        Qs[r][c] = qbase[(size_t)r * E3 + c];
    }

    // Per-query window params (broadcast across the 8 threads of each query)
    const float* pp = g_params + ((size_t)bh * TT + i) * 6;
    float bl = pp[0], br = pp[1], wbl = pp[2], wbr = pp[3], al = pp[4], fr = pp[5];
    float ar = al + 1.f;

    float m = -1e30f, l = 0.f;
    float acc[8];
#pragma unroll
    for (int cc = 0; cc < 8; cc++) acc[cc] = 0.f;

    const float* kvbase = g_qkv + (size_t)(b * TT) * E3 + h * HDD;

    for (int jt = 0; jt < TT; jt += 32) {
        __syncthreads();
#pragma unroll
        for (int idx = tid; idx < 32 * 64; idx += 256) {
            int r = idx >> 6, c = idx & 63;
            size_t row = (size_t)(jt + r) * E3;
            Ks[r][c] = kvbase[row + EE + c];
            Vs[r][c] = kvbase[row + 2 * EE + c];
        }
        __syncthreads();

        // scores: s[jj] = Q[i] . K[jt + g*4 + jj]
        float s[4];
#pragma unroll
        for (int jj = 0; jj < 4; jj++) s[jj] = 0.f;
#pragma unroll
        for (int k = 0; k < 64; k++) {
            float qv = Qs[q][k];
#pragma unroll
            for (int jj = 0; jj < 4; jj++)
                s[jj] = fmaf(qv, Ks[g * 4 + jj][k], s[jj]);
        }

        float tmax = -1e30f;
#pragma unroll
        for (int jj = 0; jj < 4; jj++) {
            float jf = (float)(jt + g * 4 + jj);
            float w = 1.f;
            if (jf == bl) w += wbl;
            if (jf == br) w += wbr;
            if (jf == al) w += 1.f - fr;
            if (jf == ar) w += fr;
            float sv = s[jj] * SCALE * w;
            if (jf < bl || jf > br) sv = -1e8f;  // segment mask, same constant as ref
            s[jj] = sv;
            tmax = fmaxf(tmax, sv);
        }
        // reduce max over the 8 threads of this query (aligned 8-lane segment)
#pragma unroll
        for (int off = 4; off >= 1; off >>= 1)
            tmax = fmaxf(tmax, __shfl_xor_sync(0xffffffffu, tmax, off, 8));

        float mnew = fmaxf(m, tmax);
        float factor = __expf(m - mnew);

        float psum = 0.f;
#pragma unroll
        for (int jj = 0; jj < 4; jj++) {
            float p = __expf(s[jj] - mnew);
            Ps[q][g * 4 + jj] = p;
            psum += p;
        }
#pragma unroll
        for (int off = 4; off >= 1; off >>= 1)
            psum += __shfl_xor_sync(0xffffffffu, psum, off, 8);

        l = l * factor + psum;
        m = mnew;
        __syncthreads();   // Ps visible to all 8 threads of each query

#pragma unroll
        for (int cc = 0; cc < 8; cc++) acc[cc] *= factor;
#pragma unroll 4
        for (int j = 0; j < 32; j++) {
            float p = Ps[q][j];
#pragma unroll
            for (int cc = 0; cc < 8; cc++)
                acc[cc] = fmaf(p, Vs[j][cc * 8 + g], acc[cc]);
        }
    }

    float inv = 1.f / l;
    float* outp = g_attn + ((size_t)(b * TT) + i) * EE + h * HDD;
#pragma unroll
    for (int cc = 0; cc < 8; cc++)
        outp[cc * 8 + g] = acc[cc] * inv;
}

// ---------------------------------------------------------------------------
extern "C" void kernel_launch(void* const* d_in, const int* in_sizes, int n_in,
                              void* d_out, int out_size)
{
    const float* x      = (const float*)d_in[0];
    const float* w_qkv  = (const float*)d_in[1];
    const float* b_qkv  = (const float*)d_in[2];
    const float* w_od   = (const float*)d_in[3];
    const float* b_od   = (const float*)d_in[4];
    const float* w_out  = (const float*)d_in[5];
    const float* b_out  = (const float*)d_in[6];
    float* out = (float*)d_out;

    float* qkv;  cudaGetSymbolAddress((void**)&qkv,  g_qkv);
    float* attn; cudaGetSymbolAddress((void**)&attn, g_attn);

    // 1) QKV = x @ w_qkv + b_qkv : (4096,512)@(512,1536)
    gemm_bias_kernel<<<dim3(E3 / 64, (BB * TT) / 64), 256>>>(
        x, w_qkv, b_qkv, qkv, BB * TT, E3, EE);

    // 2) Per-(head,query) deformable window params from Q @ w_od + b_od
    od_kernel<<<BB * TT, 128>>>(w_od, b_od);

    // 3) Flash deformable attention -> (B,T,E) layout
    attn_kernel<<<dim3(TT / 32, BHH), 256>>>();

    // 4) out = attn @ w_out + b_out : (4096,512)@(512,512)
    gemm_bias_kernel<<<dim3(EE / 64, (BB * TT) / 64), 256>>>(
        attn, w_out, b_out, out, BB * TT, EE, EE);
}

// round 2
// speedup vs baseline: 1.9223x; 1.9223x over previous
#include <cuda_runtime.h>
#include <math.h>

#define BB 2
#define TT 2048
#define EE 512
#define NHH 8
#define HDD 64
#define BHH (BB*NHH)
#define E3 (3*EE)
#define SCALE_F 0.125f

typedef unsigned long long u64;

// Scratch (no allocations allowed)
__device__ float g_qkv[(size_t)BB * TT * E3];    // 25 MB
__device__ float g_params[(size_t)BHH * TT * 6]; // per (bh,t): bl, br, wbl, wbr, al, frac
__device__ float g_attn[(size_t)BB * TT * EE];   // 8 MB

// ---------------------------------------------------------------------------
// Packed f32x2 helpers (Blackwell dual-FMA path; ptxas never auto-generates)
// ---------------------------------------------------------------------------
__device__ __forceinline__ u64 pack2(float lo, float hi) {
    u64 r; asm("mov.b64 %0, {%1,%2};" : "=l"(r) : "f"(lo), "f"(hi)); return r;
}
__device__ __forceinline__ void unpack2(u64 v, float& lo, float& hi) {
    asm("mov.b64 {%0,%1}, %2;" : "=f"(lo), "=f"(hi) : "l"(v));
}
__device__ __forceinline__ u64 fma2(u64 a, u64 b, u64 c) {
    u64 d; asm("fma.rn.f32x2 %0, %1, %2, %3;" : "=l"(d) : "l"(a), "l"(b), "l"(c)); return d;
}
__device__ __forceinline__ u64 mul2(u64 a, u64 b) {
    u64 d; asm("mul.rn.f32x2 %0, %1, %2;" : "=l"(d) : "l"(a), "l"(b)); return d;
}

// ---------------------------------------------------------------------------
// GEMM: C[M,N] = A[M,K] @ W[K,N] + bias. BM=BN=128, BK=8, 256 thr, 8x8/thread,
// FFMA2 inner loop (pairs along N).
// ---------------------------------------------------------------------------
__global__ __launch_bounds__(256) void gemm_bias_kernel(
    const float* __restrict__ A, const float* __restrict__ W,
    const float* __restrict__ bias, float* __restrict__ C,
    int M, int N, int K)
{
    __shared__ float Ast[8][132];   // transposed: [k][row]
    __shared__ float Bs[8][132];    // natural:    [k][col]

    int bm = blockIdx.y * 128;
    int bn = blockIdx.x * 128;
    int tid = threadIdx.x;
    int tx = tid & 15, ty = tid >> 4;

    u64 acc[8][4];
#pragma unroll
    for (int i = 0; i < 8; i++)
#pragma unroll
        for (int j = 0; j < 4; j++) acc[i][j] = 0ull;

    // load assignments
    int ar = tid >> 1, ac = (tid & 1) * 4;    // A: row ar, cols ac..ac+3 of BK
    int brow = tid >> 5, bc = (tid & 31) * 4; // W: row brow, cols bc..bc+3

    for (int k0 = 0; k0 < K; k0 += 8) {
        float4 av = *(const float4*)&A[(size_t)(bm + ar) * K + k0 + ac];
        float4 bv = *(const float4*)&W[(size_t)(k0 + brow) * N + bn + bc];
        __syncthreads();
        Ast[ac + 0][ar] = av.x;
        Ast[ac + 1][ar] = av.y;
        Ast[ac + 2][ar] = av.z;
        Ast[ac + 3][ar] = av.w;
        *(float4*)&Bs[brow][bc] = bv;
        __syncthreads();

#pragma unroll
        for (int k = 0; k < 8; k++) {
            float4 a0 = *(const float4*)&Ast[k][ty * 4];
            float4 a1 = *(const float4*)&Ast[k][64 + ty * 4];
            ulonglong2 b0 = *(const ulonglong2*)&Bs[k][tx * 4];
            ulonglong2 b1 = *(const ulonglong2*)&Bs[k][64 + tx * 4];
            float ai[8] = {a0.x, a0.y, a0.z, a0.w, a1.x, a1.y, a1.z, a1.w};
#pragma unroll
            for (int i = 0; i < 8; i++) {
                u64 a2 = pack2(ai[i], ai[i]);
                acc[i][0] = fma2(a2, b0.x, acc[i][0]);
                acc[i][1] = fma2(a2, b0.y, acc[i][1]);
                acc[i][2] = fma2(a2, b1.x, acc[i][2]);
                acc[i][3] = fma2(a2, b1.y, acc[i][3]);
            }
        }
    }

    float4 bias0 = *(const float4*)&bias[bn + tx * 4];
    float4 bias1 = *(const float4*)&bias[bn + 64 + tx * 4];
#pragma unroll
    for (int i = 0; i < 8; i++) {
        int row = bm + ((i < 4) ? (ty * 4 + i) : (64 + ty * 4 + (i - 4)));
        float4 o0, o1;
        unpack2(acc[i][0], o0.x, o0.y);
        unpack2(acc[i][1], o0.z, o0.w);
        unpack2(acc[i][2], o1.x, o1.y);
        unpack2(acc[i][3], o1.z, o1.w);
        o0.x += bias0.x; o0.y += bias0.y; o0.z += bias0.z; o0.w += bias0.w;
        o1.x += bias1.x; o1.y += bias1.y; o1.z += bias1.z; o1.w += bias1.w;
        *(float4*)&C[(size_t)row * N + bn + tx * 4] = o0;
        *(float4*)&C[(size_t)row * N + bn + 64 + tx * 4] = o1;
    }
}

// ---------------------------------------------------------------------------
// od kernel: per (b,t): od[16] = Q_row @ w_od + b_od -> 6 window scalars/head
// ---------------------------------------------------------------------------
__global__ __launch_bounds__(128) void od_kernel(
    const float* __restrict__ w_od, const float* __restrict__ b_od)
{
    int bt = blockIdx.x;
    int b = bt / TT, t = bt % TT;
    const float* qrow = g_qkv + (size_t)bt * E3;

    int tid = threadIdx.x;
    int c = tid & 15, r = tid >> 4;

    float partial = 0.f;
    for (int k = r; k < EE; k += 8)
        partial = fmaf(qrow[k], w_od[k * 16 + c], partial);

    __shared__ float red[128];
    __shared__ float odv[16];
    red[tid] = partial;
    __syncthreads();
    if (tid < 16) {
        float s = 0.f;
#pragma unroll
        for (int rr = 0; rr < 8; rr++) s += red[tid + 16 * rr];
        odv[tid] = s + b_od[tid];
    }
    __syncthreads();
    if (tid < NHH) {
        int h = tid;
        float off = tanhf(odv[h]) * (float)TT;
        float dur = (float)TT / (1.f + expf(-odv[h + NHH]));
        float anchor = (float)t + off;
        float start = anchor - dur;
        float end   = anchor + dur;
        float blv = floorf(start);
        float brv = ceilf(end);
        float alv = floorf(anchor);
        float frv = anchor - alv;
        float* p = g_params + ((size_t)(b * NHH + h) * TT + t) * 6;
        p[0] = blv;
        p[1] = brv;
        p[2] = blv - start;
        p[3] = end - brv;
        p[4] = alv;
        p[5] = frv;
    }
}

// ---------------------------------------------------------------------------
// Flash deformable attention. 64 queries x 64 key tile, 256 threads,
// 4x4 scores/thread with FFMA2 pairs along j. Window-union tile skipping.
// ---------------------------------------------------------------------------
__global__ __launch_bounds__(256, 2) void attn_kernel()
{
    extern __shared__ float sm[];
    float* Qs  = sm;                 // [64][65] natural
    float* KsT = Qs  + 64 * 65;      // [64 k][64 j], XOR chunk swizzle
    float* Vs  = KsT + 64 * 64;      // [64 j][68 d]
    float* Ps  = Vs  + 64 * 68;      // [64 q][68 j]
    float* Pp  = Ps  + 64 * 68;      // [64][8] params
    __shared__ int s_jt0, s_jt1;

    int qt = blockIdx.x;
    int bh = blockIdx.y;
    int b = bh >> 3, h = bh & 7;
    int tid = threadIdx.x;
    int tx = tid & 15, ty = tid >> 4;
    int q0 = qt * 64;

    // Q tile fill (coalesced scalar, stride 65)
    const float* qbase = g_qkv + ((size_t)(b * TT) + q0) * E3 + h * HDD;
#pragma unroll
    for (int it = 0; it < 16; it++) {
        int idx = it * 256 + tid;
        int r = idx >> 6, c = idx & 63;
        Qs[r * 65 + c] = qbase[(size_t)r * E3 + c];
    }
    // params
    if (tid < 64) {
        const float* p = g_params + ((size_t)bh * TT + q0 + tid) * 6;
#pragma unroll
        for (int c = 0; c < 6; c++) Pp[tid * 8 + c] = p[c];
        float lo = fmaxf(p[0], 0.f);
        float hi = fminf(p[1], (float)(TT - 1));
        Pp[tid * 8 + 6] = lo;
        Pp[tid * 8 + 7] = hi;
    }
    __syncthreads();
    if (tid == 0) {
        float jmin = 1e30f, jmax = -1e30f;
        int empty = 0;
        for (int r = 0; r < 64; r++) {
            float lo = Pp[r * 8 + 6], hi = Pp[r * 8 + 7];
            if (lo > hi) empty = 1;
            jmin = fminf(jmin, lo);
            jmax = fmaxf(jmax, hi);
        }
        if (empty) { s_jt0 = 0; s_jt1 = TT - 1; }
        else       { s_jt0 = ((int)jmin) & ~63; s_jt1 = (int)jmax; }
    }
    __syncthreads();

    float bl[4], br[4], wbl[4], wbr[4], al[4], fr[4];
#pragma unroll
    for (int i = 0; i < 4; i++) {
        int r = ty * 4 + i;
        bl[i] = Pp[r * 8 + 0]; br[i] = Pp[r * 8 + 1];
        wbl[i] = Pp[r * 8 + 2]; wbr[i] = Pp[r * 8 + 3];
        al[i] = Pp[r * 8 + 4]; fr[i] = Pp[r * 8 + 5];
    }

    float m[4], l[4];
    u64 acc[4][2];
#pragma unroll
    for (int i = 0; i < 4; i++) {
        m[i] = -1e30f; l[i] = 0.f; acc[i][0] = 0ull; acc[i][1] = 0ull;
    }

    const float* kbase = g_qkv + (size_t)(b * TT) * E3 + EE + h * HDD;
    const float* vbase = g_qkv + (size_t)(b * TT) * E3 + 2 * EE + h * HDD;
    int jt0 = s_jt0, jt1 = s_jt1;

    for (int jt = jt0; jt <= jt1; jt += 64) {
        __syncthreads();
        // K fill: k-major, XOR chunk swizzle (chunk = (j>>2) ^ (k&15))
#pragma unroll
        for (int it = 0; it < 16; it++) {
            int idx = it * 256 + tid;
            int k = idx & 63, j = idx >> 6;
            float v = kbase[(size_t)(jt + j) * E3 + k];
            int cs = (j >> 2) ^ (k & 15);
            KsT[k * 64 + cs * 4 + (j & 3)] = v;
        }
        // V fill: float4
#pragma unroll
        for (int it = 0; it < 4; it++) {
            int idx = it * 256 + tid;
            int r = idx >> 4, c4 = idx & 15;
            float4 v = *(const float4*)&vbase[(size_t)(jt + r) * E3 + c4 * 4];
            *(float4*)&Vs[r * 68 + c4 * 4] = v;
        }
        __syncthreads();

        // QK: s[4 rows][4 cols] via FFMA2 pairs along j
        u64 s2[4][2];
#pragma unroll
        for (int i = 0; i < 4; i++) { s2[i][0] = 0ull; s2[i][1] = 0ull; }
#pragma unroll 16
        for (int k = 0; k < 64; k++) {
            ulonglong2 bq = *(const ulonglong2*)&KsT[k * 64 + ((tx ^ (k & 15)) << 2)];
#pragma unroll
            for (int i = 0; i < 4; i++) {
                float a = Qs[(ty * 4 + i) * 65 + k];
                u64 a2 = pack2(a, a);
                s2[i][0] = fma2(a2, bq.x, s2[i][0]);
                s2[i][1] = fma2(a2, bq.y, s2[i][1]);
            }
        }

        // softmax bookkeeping per row
        float factor[4];
#pragma unroll
        for (int i = 0; i < 4; i++) {
            float s[4];
            unpack2(s2[i][0], s[0], s[1]);
            unpack2(s2[i][1], s[2], s[3]);
            float tmax = -1e30f;
#pragma unroll
            for (int jj = 0; jj < 4; jj++) {
                float jf = (float)(jt + tx * 4 + jj);
                float w = 1.f;
                if (jf == bl[i]) w += wbl[i];
                if (jf == br[i]) w += wbr[i];
                if (jf == al[i]) w += 1.f - fr[i];
                if (jf == al[i] + 1.f) w += fr[i];
                float sv = s[jj] * SCALE_F * w;
                if (jf < bl[i] || jf > br[i]) sv = -1e8f;
                s[jj] = sv;
                tmax = fmaxf(tmax, sv);
            }
#pragma unroll
            for (int off = 8; off >= 1; off >>= 1)
                tmax = fmaxf(tmax, __shfl_xor_sync(0xffffffffu, tmax, off));
            float mnew = fmaxf(m[i], tmax);
            factor[i] = __expf(m[i] - mnew);
            float4 pv;
            pv.x = __expf(s[0] - mnew);
            pv.y = __expf(s[1] - mnew);
            pv.z = __expf(s[2] - mnew);
            pv.w = __expf(s[3] - mnew);
            float psum = pv.x + pv.y + pv.z + pv.w;
#pragma unroll
            for (int off = 8; off >= 1; off >>= 1)
                psum += __shfl_xor_sync(0xffffffffu, psum, off);
            l[i] = l[i] * factor[i] + psum;
            m[i] = mnew;
            *(float4*)&Ps[(ty * 4 + i) * 68 + tx * 4] = pv;
        }
        __syncthreads();

        // rescale accumulators
#pragma unroll
        for (int i = 0; i < 4; i++) {
            u64 f2 = pack2(factor[i], factor[i]);
            acc[i][0] = mul2(acc[i][0], f2);
            acc[i][1] = mul2(acc[i][1], f2);
        }
        // PV: acc[rows][4 dims] += P * V
#pragma unroll 8
        for (int j = 0; j < 64; j++) {
            ulonglong2 vq = *(const ulonglong2*)&Vs[j * 68 + tx * 4];
#pragma unroll
            for (int i = 0; i < 4; i++) {
                float a = Ps[(ty * 4 + i) * 68 + j];
                u64 a2 = pack2(a, a);
                acc[i][0] = fma2(a2, vq.x, acc[i][0]);
                acc[i][1] = fma2(a2, vq.y, acc[i][1]);
            }
        }
    }

    float* ob = g_attn + ((size_t)(b * TT) + q0) * EE + h * HDD;
#pragma unroll
    for (int i = 0; i < 4; i++) {
        float inv = 1.f / l[i];
        float4 o;
        unpack2(acc[i][0], o.x, o.y);
        unpack2(acc[i][1], o.z, o.w);
        o.x *= inv; o.y *= inv; o.z *= inv; o.w *= inv;
        *(float4*)&ob[(size_t)(ty * 4 + i) * EE + tx * 4] = o;
    }
}

// ---------------------------------------------------------------------------
extern "C" void kernel_launch(void* const* d_in, const int* in_sizes, int n_in,
                              void* d_out, int out_size)
{
    const float* x      = (const float*)d_in[0];
    const float* w_qkv  = (const float*)d_in[1];
    const float* b_qkv  = (const float*)d_in[2];
    const float* w_od   = (const float*)d_in[3];
    const float* b_od   = (const float*)d_in[4];
    const float* w_out  = (const float*)d_in[5];
    const float* b_out  = (const float*)d_in[6];
    float* out = (float*)d_out;

    float* qkv;  cudaGetSymbolAddress((void**)&qkv,  g_qkv);
    float* attn; cudaGetSymbolAddress((void**)&attn, g_attn);

    static int attn_smem = 0;
    if (!attn_smem) {
        attn_smem = (64 * 65 + 64 * 64 + 64 * 68 + 64 * 68 + 64 * 8) * 4;
        cudaFuncSetAttribute(attn_kernel,
                             cudaFuncAttributeMaxDynamicSharedMemorySize, attn_smem);
    }
    int smem = (64 * 65 + 64 * 64 + 64 * 68 + 64 * 68 + 64 * 8) * 4;

    // 1) QKV = x @ w_qkv + b_qkv : (4096,512)@(512,1536)
    gemm_bias_kernel<<<dim3(E3 / 128, (BB * TT) / 128), 256>>>(
        x, w_qkv, b_qkv, qkv, BB * TT, E3, EE);

    // 2) window params
    od_kernel<<<BB * TT, 128>>>(w_od, b_od);

    // 3) flash deformable attention
    attn_kernel<<<dim3(TT / 64, BHH), 256, smem>>>();

    // 4) out = attn @ w_out + b_out : (4096,512)@(512,512)
    gemm_bias_kernel<<<dim3(EE / 128, (BB * TT) / 128), 256>>>(
        attn, w_out, b_out, out, BB * TT, EE, EE);
}